// round 3
// baseline (speedup 1.0000x reference)
#include <cuda_runtime.h>
#include <math.h>

#define KDIM 512
#define NTHREADS 256
#define BLOCKS_PER_SM 6
#define NBLOCKS (148 * BLOCKS_PER_SM)   // 888 — exactly one full wave
#define WARPS_PER_BLOCK (NTHREADS / 32)

// Deterministic per-block partial sums (no device allocation allowed).
__device__ double g_partials[NBLOCKS];
__device__ unsigned int g_count = 0;   // reset by last block each call -> graph-replay safe

__global__ __launch_bounds__(NTHREADS, BLOCKS_PER_SM) void sce_main_kernel(
    const float* __restrict__ input,
    const float* __restrict__ target,
    const float* __restrict__ weight,
    float* __restrict__ out,
    int n_rows)
{
    __shared__ float s_w[KDIM];
    __shared__ double s_warp[WARPS_PER_BLOCK];
    __shared__ bool s_last;

    const int tid = threadIdx.x;
    for (int i = tid; i < KDIM; i += NTHREADS) s_w[i] = weight[i];
    __syncthreads();

    const int warp = tid >> 5;
    const int lane = tid & 31;
    const int gwarp = blockIdx.x * WARPS_PER_BLOCK + warp;
    const int nwarps = NBLOCKS * WARPS_PER_BLOCK;

    // Per-lane weights are loop-invariant: lane reads the same 16 w values every row.
    float wv[16];
    #pragma unroll
    for (int j = 0; j < 4; j++) {
        const int c = (lane + 32 * j) * 4;
        wv[4 * j + 0] = s_w[c + 0];
        wv[4 * j + 1] = s_w[c + 1];
        wv[4 * j + 2] = s_w[c + 2];
        wv[4 * j + 3] = s_w[c + 3];
    }

    double acc = 0.0;

    for (int row = gwarp; row < n_rows; row += nwarps) {
        const float4* xr = (const float4*)(input + (size_t)row * KDIM);
        const float4* tr = (const float4*)(target + (size_t)row * KDIM);

        float4 x[4];
        // Front-batched streaming loads (read-once data: evict-first).
        #pragma unroll
        for (int j = 0; j < 4; j++) x[j] = __ldcs(&xr[lane + 32 * j]);

        // Consume target immediately — tw/twx don't depend on the row max,
        // so t never occupies registers beyond one float4.
        float tw = 0.f, twx = 0.f;
        #pragma unroll
        for (int j = 0; j < 4; j++) {
            const float4 t = __ldcs(&tr[lane + 32 * j]);
            const float a0 = t.x * wv[4 * j + 0], a1 = t.y * wv[4 * j + 1];
            const float a2 = t.z * wv[4 * j + 2], a3 = t.w * wv[4 * j + 3];
            tw  += (a0 + a1) + (a2 + a3);
            twx += (a0 * x[j].x + a1 * x[j].y) + (a2 * x[j].z + a3 * x[j].w);
        }

        // Row max over x
        float m = -INFINITY;
        #pragma unroll
        for (int j = 0; j < 4; j++)
            m = fmaxf(m, fmaxf(fmaxf(x[j].x, x[j].y), fmaxf(x[j].z, x[j].w)));
        #pragma unroll
        for (int o = 16; o > 0; o >>= 1)
            m = fmaxf(m, __shfl_xor_sync(0xFFFFFFFFu, m, o));

        // Sum of exp(x - m)
        float se = 0.f;
        #pragma unroll
        for (int j = 0; j < 4; j++) {
            se += __expf(x[j].x - m) + __expf(x[j].y - m)
                + __expf(x[j].z - m) + __expf(x[j].w - m);
        }

        #pragma unroll
        for (int o = 16; o > 0; o >>= 1) {
            se  += __shfl_xor_sync(0xFFFFFFFFu, se, o);
            tw  += __shfl_xor_sync(0xFFFFFFFFu, tw, o);
            twx += __shfl_xor_sync(0xFFFFFFFFu, twx, o);
        }

        const float lse = m + __logf(se);
        acc += (double)(tw * lse - twx);   // per_row = sum t*w*(lse - x)
    }

    if (lane == 0) s_warp[warp] = acc;
    __syncthreads();
    if (tid == 0) {
        double b = 0.0;
        #pragma unroll
        for (int i = 0; i < WARPS_PER_BLOCK; i++) b += s_warp[i];
        g_partials[blockIdx.x] = b;
        __threadfence();
        unsigned int prev = atomicAdd(&g_count, 1u);
        s_last = (prev == NBLOCKS - 1);
    }
    __syncthreads();

    // Last block performs the deterministic final reduction.
    if (s_last) {
        __shared__ double s_red[NTHREADS];
        double a = 0.0;
        for (int i = tid; i < NBLOCKS; i += NTHREADS)
            a += __ldcg(&g_partials[i]);
        s_red[tid] = a;
        __syncthreads();
        for (int o = NTHREADS / 2; o > 0; o >>= 1) {
            if (tid < o) s_red[tid] += s_red[tid + o];
            __syncthreads();
        }
        if (tid == 0) {
            out[0] = (float)(s_red[0] / (double)n_rows);
            g_count = 0;   // reset for next graph replay
            __threadfence();
        }
    }
}

extern "C" void kernel_launch(void* const* d_in, const int* in_sizes, int n_in,
                              void* d_out, int out_size)
{
    const float* input  = (const float*)d_in[0];
    const float* target = (const float*)d_in[1];
    const float* weight = (const float*)d_in[2];
    float* out = (float*)d_out;

    const int n_rows = in_sizes[0] / KDIM;

    sce_main_kernel<<<NBLOCKS, NTHREADS>>>(input, target, weight, out, n_rows);
}

// round 4
// speedup vs baseline: 1.1284x; 1.1284x over previous
#include <cuda_runtime.h>
#include <math.h>

#define KDIM 512
#define NTHREADS 256
#define BLOCKS_PER_SM 5
#define NBLOCKS (148 * BLOCKS_PER_SM)   // 740 — exactly one full wave at 5 blocks/SM
#define WARPS_PER_BLOCK (NTHREADS / 32)

// Deterministic per-block partial sums (no device allocation allowed).
__device__ double g_partials[NBLOCKS];
__device__ unsigned int g_count = 0;   // reset by last block each call -> graph-replay safe

__global__ __launch_bounds__(NTHREADS, BLOCKS_PER_SM) void sce_main_kernel(
    const float* __restrict__ input,
    const float* __restrict__ target,
    const float* __restrict__ weight,
    float* __restrict__ out,
    int n_rows)
{
    __shared__ float s_w[KDIM];
    __shared__ double s_warp[WARPS_PER_BLOCK];
    __shared__ bool s_last;

    const int tid = threadIdx.x;
    // Stage weight vector in shared (2 KB).
    for (int i = tid; i < KDIM; i += NTHREADS) s_w[i] = weight[i];
    __syncthreads();

    const int warp = tid >> 5;
    const int lane = tid & 31;
    const int gwarp = blockIdx.x * WARPS_PER_BLOCK + warp;
    const int nwarps = NBLOCKS * WARPS_PER_BLOCK;

    double acc = 0.0;

    for (int row = gwarp; row < n_rows; row += nwarps) {
        const float4* xr = (const float4*)(input + (size_t)row * KDIM);
        const float4* tr = (const float4*)(target + (size_t)row * KDIM);

        float4 x[4], t[4];
        // 8 back-to-back 128B coalesced loads per warp — front-batched for MLP.
        #pragma unroll
        for (int j = 0; j < 4; j++) x[j] = xr[lane + 32 * j];
        #pragma unroll
        for (int j = 0; j < 4; j++) t[j] = tr[lane + 32 * j];

        // Row max
        float m = -INFINITY;
        #pragma unroll
        for (int j = 0; j < 4; j++) {
            m = fmaxf(m, fmaxf(fmaxf(x[j].x, x[j].y), fmaxf(x[j].z, x[j].w)));
        }
        #pragma unroll
        for (int o = 16; o > 0; o >>= 1)
            m = fmaxf(m, __shfl_xor_sync(0xFFFFFFFFu, m, o));

        // Fused: sum exp(x-m), sum t*w, sum t*w*x (single register pass)
        float se = 0.f, tw = 0.f, twx = 0.f;
        #pragma unroll
        for (int j = 0; j < 4; j++) {
            const int c = (lane + 32 * j) * 4;
            const float w0 = s_w[c + 0], w1 = s_w[c + 1];
            const float w2 = s_w[c + 2], w3 = s_w[c + 3];
            se += __expf(x[j].x - m) + __expf(x[j].y - m)
                + __expf(x[j].z - m) + __expf(x[j].w - m);
            const float a0 = t[j].x * w0, a1 = t[j].y * w1;
            const float a2 = t[j].z * w2, a3 = t[j].w * w3;
            tw  += (a0 + a1) + (a2 + a3);
            twx += (a0 * x[j].x + a1 * x[j].y) + (a2 * x[j].z + a3 * x[j].w);
        }
        #pragma unroll
        for (int o = 16; o > 0; o >>= 1) {
            se  += __shfl_xor_sync(0xFFFFFFFFu, se, o);
            tw  += __shfl_xor_sync(0xFFFFFFFFu, tw, o);
            twx += __shfl_xor_sync(0xFFFFFFFFu, twx, o);
        }

        const float lse = m + __logf(se);
        acc += (double)(tw * lse - twx);   // per_row = sum t*w*(lse - x)
    }

    if (lane == 0) s_warp[warp] = acc;
    __syncthreads();
    if (tid == 0) {
        double b = 0.0;
        #pragma unroll
        for (int i = 0; i < WARPS_PER_BLOCK; i++) b += s_warp[i];
        g_partials[blockIdx.x] = b;
        __threadfence();
        unsigned int prev = atomicAdd(&g_count, 1u);
        s_last = (prev == NBLOCKS - 1);
    }
    __syncthreads();

    // Last block performs the deterministic final reduction.
    if (s_last) {
        __shared__ double s_red[NTHREADS];
        double a = 0.0;
        for (int i = tid; i < NBLOCKS; i += NTHREADS)
            a += __ldcg(&g_partials[i]);
        s_red[tid] = a;
        __syncthreads();
        for (int o = NTHREADS / 2; o > 0; o >>= 1) {
            if (tid < o) s_red[tid] += s_red[tid + o];
            __syncthreads();
        }
        if (tid == 0) {
            out[0] = (float)(s_red[0] / (double)n_rows);
            g_count = 0;   // reset for next graph replay
            __threadfence();
        }
    }
}

extern "C" void kernel_launch(void* const* d_in, const int* in_sizes, int n_in,
                              void* d_out, int out_size)
{
    const float* input  = (const float*)d_in[0];
    const float* target = (const float*)d_in[1];
    const float* weight = (const float*)d_in[2];
    float* out = (float*)d_out;

    const int n_rows = in_sizes[0] / KDIM;

    sce_main_kernel<<<NBLOCKS, NTHREADS>>>(input, target, weight, out, n_rows);
}